// round 3
// baseline (speedup 1.0000x reference)
#include <cuda_runtime.h>

#define BB 2
#define HH 512
#define WW 512
#define HW (HH*WW)            // 262144
#define CHW ((size_t)256*HW)
#define NPIX (BB*HW)          // 524288
#define GRID 256
#define TPB 512
#define NTH (GRID*TPB)        // 131072 threads, 4 px each

// ---------------- device scratch (static, no allocation) ----------------
__device__ unsigned      g_img[NPIX];          // packed r|g<<8|b<<16, 2 MB
__device__ unsigned char g_alpha[2][NPIX];     // ping-pong alpha, 1 MB
__device__ unsigned      g_mn[BB], g_mx[BB];   // order-mapped min/max
__device__ unsigned      g_fgsum[6][BB][3];    // exact integer fg color sums
__device__ unsigned      g_fgcnt[6][BB];       // exact integer fg counts
__device__ unsigned      g_tot[BB][3];         // exact integer total sums
__device__ unsigned      g_barcnt;             // grid barrier counter

__device__ __forceinline__ unsigned f2ord(float f) {
    unsigned u = __float_as_uint(f);
    return (u & 0x80000000u) ? ~u : (u | 0x80000000u);
}
__device__ __forceinline__ float ord2f(unsigned u) {
    return __uint_as_float((u & 0x80000000u) ? (u ^ 0x80000000u) : ~u);
}
__device__ __forceinline__ float normq(float f, float mn, float den) {
    float v = __fmul_rn(__fdiv_rn(__fsub_rn(f, mn), den), 255.0f);
    v = floorf(v);
    return fminf(fmaxf(v, 0.0f), 255.0f);
}

// software grid barrier: 256 blocks, all resident (launch_bounds(512,2) => >=296 slots)
__device__ __forceinline__ void gridbar(unsigned target) {
    __threadfence();
    __syncthreads();
    if (threadIdx.x == 0) {
        unsigned a = atomicAdd(&g_barcnt, 1u) + 1u;
        if (a < target)
            while (*(volatile unsigned*)&g_barcnt < target) { __nanosleep(32); }
    }
    __syncthreads();
}

// ---------------- kernel 0: zero accumulators + barrier counter ----------------
__global__ void k_init() {
    int t = threadIdx.x;
    if (t < 36) ((unsigned*)g_fgsum)[t] = 0u;
    if (t < 12) ((unsigned*)g_fgcnt)[t] = 0u;
    if (t < 6)  ((unsigned*)g_tot)[t] = 0u;
    if (t < BB) { g_mn[t] = 0xFFFFFFFFu; g_mx[t] = 0u; }
    if (t == 0) g_barcnt = 0u;
}

// ---------------- whole pipeline, one persistent kernel ----------------
__global__ void __launch_bounds__(TPB, 2)
k_fused(const float* __restrict__ feat, const int* __restrict__ mask,
        float* __restrict__ out) {
    const int t    = threadIdx.x;
    const int tid  = blockIdx.x * TPB + t;
    const int lane = t & 31, warp = t >> 5;   // 16 warps
    unsigned bar = 0;

    __shared__ unsigned s_u[32];              // warp min/max partials
    __shared__ unsigned s_su[7 * 16];         // warp sum partials
    __shared__ float    s_means[8];

    // ======== phase 1: per-batch min/max over first 3 channels ========
    {
        const int bt  = blockIdx.x >> 7;                       // blocks 0..127 -> batch 0
        const int idx = (blockIdx.x & 127) * TPB + t;          // 0..65535
        const float4* s = (const float4*)(feat + (size_t)bt * CHW);
        unsigned mn = 0xFFFFFFFFu, mx = 0u;
        #pragma unroll
        for (int it = 0; it < 3; it++) {                       // 3*HW/4 = 196608 float4 / 65536 thr
            float4 v = s[idx + it * 65536];
            unsigned u;
            u = f2ord(v.x); mn = min(mn, u); mx = max(mx, u);
            u = f2ord(v.y); mn = min(mn, u); mx = max(mx, u);
            u = f2ord(v.z); mn = min(mn, u); mx = max(mx, u);
            u = f2ord(v.w); mn = min(mn, u); mx = max(mx, u);
        }
        mn = __reduce_min_sync(0xFFFFFFFFu, mn);
        mx = __reduce_max_sync(0xFFFFFFFFu, mx);
        if (lane == 0) { s_u[warp] = mn; s_u[16 + warp] = mx; }
        __syncthreads();
        if (warp == 0) {
            unsigned wmn = (lane < 16) ? s_u[lane]      : 0xFFFFFFFFu;
            unsigned wmx = (lane < 16) ? s_u[16 + lane] : 0u;
            wmn = __reduce_min_sync(0xFFFFFFFFu, wmn);
            wmx = __reduce_max_sync(0xFFFFFFFFu, wmx);
            if (lane == 0) { atomicMin(&g_mn[bt], wmn); atomicMax(&g_mx[bt], wmx); }
        }
    }
    bar += GRID; gridbar(bar);

    // fixed geometry for this thread's 4 pixels
    const int p0 = tid * 4;
    const int b  = p0 >> 18;
    const int r  = p0 & (HW - 1);
    const int y  = r >> 9;
    const int x0 = r & 511;
    const bool yb = (y < 51) | (y >= 461);
    const bool yc = (y >= 230) & (y < 281);
    unsigned char fixedv[4], fixval[4];
    #pragma unroll
    for (int j = 0; j < 4; j++) {
        int xj = x0 + j;
        bool border = yb | (xj < 51) | (xj >= 461);
        bool center = yc & (xj >= 230) & (xj < 281);
        fixedv[j] = border | center;
        fixval[j] = center ? 1 : 0;
    }

    // ======== phase 2: normalize + trimap + alpha0 + exact sums ========
    unsigned px[4];
    {
        if (t == 0) {
            float mnf = ord2f(__ldcg(&g_mn[b]));
            float mxf = ord2f(__ldcg(&g_mx[b]));
            s_means[0] = mnf;
            s_means[1] = __fadd_rn(__fsub_rn(mxf, mnf), 1e-12f);
        }
        __syncthreads();
        float mnf = s_means[0], den = s_means[1];
        const float* fb = feat + (size_t)b * CHW;
        float4 c0 = *(const float4*)(fb + r);
        float4 c1 = *(const float4*)(fb + HW + r);
        float4 c2 = *(const float4*)(fb + 2 * HW + r);
        int4   m  = *(const int4*)(mask + p0);
        float f0[4] = {c0.x, c0.y, c0.z, c0.w};
        float f1[4] = {c1.x, c1.y, c1.z, c1.w};
        float f2[4] = {c2.x, c2.y, c2.z, c2.w};
        int   mk[4] = {m.x, m.y, m.z, m.w};

        unsigned av[4];
        unsigned s0 = 0, s1 = 0, s2 = 0, cnt = 0, t0 = 0, t1 = 0, t2 = 0;
        #pragma unroll
        for (int j = 0; j < 4; j++) {
            unsigned q0 = (unsigned)normq(f0[j], mnf, den);
            unsigned q1 = (unsigned)normq(f1[j], mnf, den);
            unsigned q2 = (unsigned)normq(f2[j], mnf, den);
            unsigned a = fixedv[j] ? (unsigned)fixval[j] : (mk[j] == 1 ? 1u : 0u);
            px[j] = q0 | (q1 << 8) | (q2 << 16);
            av[j] = a;
            s0 += q0 * a; s1 += q1 * a; s2 += q2 * a; cnt += a;
            t0 += q0; t1 += q1; t2 += q2;
        }
        *(uint4*)&g_img[p0] = make_uint4(px[0], px[1], px[2], px[3]);
        __stcg((unsigned*)&g_alpha[0][p0],
               av[0] | (av[1] << 8) | (av[2] << 16) | (av[3] << 24));

        unsigned v[7] = {s0, s1, s2, cnt, t0, t1, t2};
        #pragma unroll
        for (int j = 0; j < 7; j++) {
            unsigned w = __reduce_add_sync(0xFFFFFFFFu, v[j]);
            if (lane == 0) s_su[j * 16 + warp] = w;
        }
        __syncthreads();
        if (warp == 0) {
            #pragma unroll
            for (int j = 0; j < 7; j++) {
                unsigned acc = (lane < 16) ? s_su[j * 16 + lane] : 0u;
                acc = __reduce_add_sync(0xFFFFFFFFu, acc);
                if (lane == 0) {
                    if (j < 3)      atomicAdd(&g_fgsum[0][b][j], acc);
                    else if (j == 3) atomicAdd(&g_fgcnt[0][b], acc);
                    else            atomicAdd(&g_tot[b][j - 4], acc);
                }
            }
        }
    }
    bar += GRID; gridbar(bar);

    // ======== phase 3: 5 ICM iterations ========
    for (int k = 0; k < 5; k++) {
        const bool last = (k == 4);
        if (t == 0) {
            unsigned cnt = __ldcg(&g_fgcnt[k][b]);
            unsigned fs0 = __ldcg(&g_fgsum[k][b][0]);
            unsigned fs1 = __ldcg(&g_fgsum[k][b][1]);
            unsigned fs2 = __ldcg(&g_fgsum[k][b][2]);
            unsigned tt0 = __ldcg(&g_tot[b][0]);
            unsigned tt1 = __ldcg(&g_tot[b][1]);
            unsigned tt2 = __ldcg(&g_tot[b][2]);
            float cntf = (float)cnt;
            float fgc = __fadd_rn(cntf, 1e-6f);
            float bgc = __fadd_rn(__fsub_rn((float)HW, cntf), 1e-6f);
            s_means[0] = __fdiv_rn((float)fs0, fgc);
            s_means[1] = __fdiv_rn((float)fs1, fgc);
            s_means[2] = __fdiv_rn((float)fs2, fgc);
            s_means[3] = __fdiv_rn((float)(tt0 - fs0), bgc);
            s_means[4] = __fdiv_rn((float)(tt1 - fs1), bgc);
            s_means[5] = __fdiv_rn((float)(tt2 - fs2), bgc);
        }
        __syncthreads();
        const float fm0 = s_means[0], fm1 = s_means[1], fm2 = s_means[2];
        const float bm0 = s_means[3], bm1 = s_means[4], bm2 = s_means[5];

        const unsigned char* __restrict__ A  = g_alpha[k & 1];
        unsigned char* __restrict__       An = g_alpha[(k + 1) & 1];

        unsigned selfv = __ldcg((const unsigned*)(A + p0));
        unsigned upv   = (y > 0)   ? __ldcg((const unsigned*)(A + p0 - WW)) : selfv;
        unsigned dnv   = (y < 511) ? __ldcg((const unsigned*)(A + p0 + WW)) : selfv;
        int sb[6];
        sb[1] =  selfv        & 255; sb[2] = (selfv >> 8)  & 255;
        sb[3] = (selfv >> 16) & 255; sb[4] = (selfv >> 24) & 255;
        sb[0] = (x0 > 0)   ? (int)__ldcg(A + p0 - 1) : sb[1];
        sb[5] = (x0 < 508) ? (int)__ldcg(A + p0 + 4) : sb[4];
        int ub[4] = { (int)(upv & 255), (int)((upv >> 8) & 255),
                      (int)((upv >> 16) & 255), (int)((upv >> 24) & 255) };
        int db[4] = { (int)(dnv & 255), (int)((dnv >> 8) & 255),
                      (int)((dnv >> 16) & 255), (int)((dnv >> 24) & 255) };

        unsigned newa[4];
        unsigned s0 = 0, s1 = 0, s2 = 0, cnt = 0;
        #pragma unroll
        for (int j = 0; j < 4; j++) {
            unsigned q0 =  px[j]        & 255;
            unsigned q1 = (px[j] >> 8)  & 255;
            unsigned q2 = (px[j] >> 16) & 255;
            float i0 = (float)q0, i1 = (float)q1, i2 = (float)q2;
            int n = ub[j] + db[j] + sb[j] + sb[j + 2];
            float pw = (float)(25 * n - 50);       // == 50*(2*(n*0.25)-1) exactly

            float d0 = __fsub_rn(i0, fm0), d1 = __fsub_rn(i1, fm1), d2 = __fsub_rn(i2, fm2);
            float dfg = __fadd_rn(__fadd_rn(__fmul_rn(d0, d0), __fmul_rn(d1, d1)),
                                  __fmul_rn(d2, d2));
            float e0 = __fsub_rn(i0, bm0), e1 = __fsub_rn(i1, bm1), e2 = __fsub_rn(i2, bm2);
            float dbg = __fadd_rn(__fadd_rn(__fmul_rn(e0, e0), __fmul_rn(e1, e1)),
                                  __fmul_rn(e2, e2));
            float score = __fadd_rn(__fsub_rn(dbg, dfg), pw);

            unsigned a = fixedv[j] ? (unsigned)fixval[j] : (score > 0.0f ? 1u : 0u);
            newa[j] = a;
            s0 += q0 * a; s1 += q1 * a; s2 += q2 * a; cnt += a;
        }
        __stcg((unsigned*)(An + p0),
               newa[0] | (newa[1] << 8) | (newa[2] << 16) | (newa[3] << 24));

        if (last) {
            *(float4*)(out + p0) = make_float4((float)newa[0], (float)newa[1],
                                               (float)newa[2], (float)newa[3]);
        } else {
            unsigned v[4] = {s0, s1, s2, cnt};
            #pragma unroll
            for (int j = 0; j < 4; j++) {
                unsigned w = __reduce_add_sync(0xFFFFFFFFu, v[j]);
                if (lane == 0) s_su[j * 16 + warp] = w;
            }
            __syncthreads();
            if (warp == 0) {
                #pragma unroll
                for (int j = 0; j < 4; j++) {
                    unsigned acc = (lane < 16) ? s_su[j * 16 + lane] : 0u;
                    acc = __reduce_add_sync(0xFFFFFFFFu, acc);
                    if (lane == 0) {
                        if (j < 3) atomicAdd(&g_fgsum[k + 1][b][j], acc);
                        else       atomicAdd(&g_fgcnt[k + 1][b], acc);
                    }
                }
            }
            bar += GRID; gridbar(bar);
        }
    }
}

extern "C" void kernel_launch(void* const* d_in, const int* in_sizes, int n_in,
                              void* d_out, int out_size) {
    const float* feat = (const float*)d_in[0];
    const int*   mask = (const int*)d_in[1];
    float*       out  = (float*)d_out;

    k_init<<<1, 64>>>();
    k_fused<<<GRID, TPB>>>(feat, mask, out);
}

// round 5
// speedup vs baseline: 1.3884x; 1.3884x over previous
#include <cuda_runtime.h>

#define BB 2
#define HH 512
#define WW 512
#define HW (HH*WW)            // 262144
#define CHW ((size_t)256*HW)
#define NPIX (BB*HW)          // 524288
#define GRID 256
#define TPB 256               // 65536 threads, 8 px each; block owns 4 rows

// ---------------- device scratch (static, no allocation) ----------------
__device__ unsigned char g_alpha[2][NPIX];     // only boundary rows actually used
__device__ unsigned g_mn[BB], g_mx[BB];        // order-mapped min/max
__device__ unsigned g_fgsum[6][BB][3];         // exact integer fg color sums
__device__ unsigned g_fgcnt[6][BB];            // exact integer fg counts
__device__ unsigned g_tot[BB][3];              // exact integer total sums
__device__ unsigned g_barcnt;                  // grid barrier counter

__device__ __forceinline__ unsigned f2ord(float f) {
    unsigned u = __float_as_uint(f);
    return (u & 0x80000000u) ? ~u : (u | 0x80000000u);
}
__device__ __forceinline__ float ord2f(unsigned u) {
    return __uint_as_float((u & 0x80000000u) ? (u ^ 0x80000000u) : ~u);
}
__device__ __forceinline__ float normq(float f, float mn, float den) {
    float v = __fmul_rn(__fdiv_rn(__fsub_rn(f, mn), den), 255.0f);
    v = floorf(v);
    return fminf(fmaxf(v, 0.0f), 255.0f);
}

// software grid barrier: 256 blocks <= 148 SMs * 2 resident slots
__device__ __forceinline__ void gridbar(unsigned target) {
    __threadfence();
    __syncthreads();
    if (threadIdx.x == 0) {
        unsigned a = atomicAdd(&g_barcnt, 1u) + 1u;
        if (a < target)
            while (*(volatile unsigned*)&g_barcnt < target) { }
    }
    __syncthreads();
}

// ---------------- kernel 0: zero accumulators + barrier counter ----------------
__global__ void k_init() {
    int t = threadIdx.x;
    if (t < 36) ((unsigned*)g_fgsum)[t] = 0u;
    if (t < 12) ((unsigned*)g_fgcnt)[t] = 0u;
    if (t < 6)  ((unsigned*)g_tot)[t] = 0u;
    if (t < BB) { g_mn[t] = 0xFFFFFFFFu; g_mx[t] = 0u; }
    if (t == 0) g_barcnt = 0u;
}

// ---------------- whole pipeline, one persistent kernel ----------------
__global__ void __launch_bounds__(TPB, 2)
k_fused(const float* __restrict__ feat, const int* __restrict__ mask,
        float* __restrict__ out) {
    const int t    = threadIdx.x;
    const int lane = t & 31, warp = t >> 5;    // 8 warps
    const int tid  = blockIdx.x * TPB + t;
    const int p0   = tid * 8;
    const int b    = p0 >> 18;
    const int r    = p0 & (HW - 1);
    const int y    = r >> 9;
    const int x0   = r & 511;
    const int ry   = t >> 6;                   // local row 0..3
    unsigned bar = 0;

    __shared__ unsigned char s_alpha[2][4][512];   // double-buffered alpha tile
    __shared__ unsigned s_su[7 * 8];
    __shared__ float    s_means[8];
    __shared__ unsigned s_u[16];

    // trimap bitmasks for this thread's 8 px
    unsigned fixmask = 0, cenmask = 0;
    {
        bool yb = (y < 51) | (y >= 461);
        bool yc = (y >= 230) & (y < 281);
        #pragma unroll
        for (int j = 0; j < 8; j++) {
            int xj = x0 + j;
            bool border = yb | (xj < 51) | (xj >= 461);
            bool center = yc & (xj >= 230) & (xj < 281);
            fixmask |= (unsigned)(border | center) << j;
            cenmask |= (unsigned)center << j;
        }
    }

    // ======== phase 1: load own pixels (3 channels) + mask; global min/max ========
    const float* fb = feat + (size_t)b * CHW;
    float f0[8], f1[8], f2[8];
    {
        float4 v;
        v = *(const float4*)(fb + r);              f0[0]=v.x; f0[1]=v.y; f0[2]=v.z; f0[3]=v.w;
        v = *(const float4*)(fb + r + 4);          f0[4]=v.x; f0[5]=v.y; f0[6]=v.z; f0[7]=v.w;
        v = *(const float4*)(fb + HW + r);         f1[0]=v.x; f1[1]=v.y; f1[2]=v.z; f1[3]=v.w;
        v = *(const float4*)(fb + HW + r + 4);     f1[4]=v.x; f1[5]=v.y; f1[6]=v.z; f1[7]=v.w;
        v = *(const float4*)(fb + 2*HW + r);       f2[0]=v.x; f2[1]=v.y; f2[2]=v.z; f2[3]=v.w;
        v = *(const float4*)(fb + 2*HW + r + 4);   f2[4]=v.x; f2[5]=v.y; f2[6]=v.z; f2[7]=v.w;
    }
    unsigned mbits;
    {
        int4 m0 = *(const int4*)(mask + p0);
        int4 m1 = *(const int4*)(mask + p0 + 4);
        mbits = (m0.x==1 ? 1u:0u) | (m0.y==1 ? 2u:0u) | (m0.z==1 ? 4u:0u) | (m0.w==1 ? 8u:0u)
              | (m1.x==1 ?16u:0u) | (m1.y==1 ?32u:0u) | (m1.z==1 ?64u:0u) | (m1.w==1?128u:0u);
    }
    {
        unsigned mn = 0xFFFFFFFFu, mx = 0u;
        #pragma unroll
        for (int j = 0; j < 8; j++) {
            unsigned u;
            u = f2ord(f0[j]); mn = min(mn, u); mx = max(mx, u);
            u = f2ord(f1[j]); mn = min(mn, u); mx = max(mx, u);
            u = f2ord(f2[j]); mn = min(mn, u); mx = max(mx, u);
        }
        mn = __reduce_min_sync(0xFFFFFFFFu, mn);
        mx = __reduce_max_sync(0xFFFFFFFFu, mx);
        if (lane == 0) { s_u[warp] = mn; s_u[8 + warp] = mx; }
        __syncthreads();
        if (warp == 0) {
            unsigned wmn = (lane < 8) ? s_u[lane]     : 0xFFFFFFFFu;
            unsigned wmx = (lane < 8) ? s_u[8 + lane] : 0u;
            wmn = __reduce_min_sync(0xFFFFFFFFu, wmn);
            wmx = __reduce_max_sync(0xFFFFFFFFu, wmx);
            if (lane == 0) { atomicMin(&g_mn[b], wmn); atomicMax(&g_mx[b], wmx); }
        }
    }
    bar += GRID; gridbar(bar);

    // ======== phase 2: normalize (from registers) + alpha0 + exact sums ========
    unsigned px[8];
    unsigned al, ah;                       // own alpha, 8 bytes packed
    {
        if (t == 0) {
            float mnf = ord2f(__ldcg(&g_mn[b]));
            float mxf = ord2f(__ldcg(&g_mx[b]));
            s_means[0] = mnf;
            s_means[1] = __fadd_rn(__fsub_rn(mxf, mnf), 1e-12f);
        }
        __syncthreads();
        const float mnf = s_means[0], den = s_means[1];

        al = 0; ah = 0;
        unsigned s0=0, s1=0, s2=0, cnt=0, u0=0, u1=0, u2=0;
        #pragma unroll
        for (int j = 0; j < 8; j++) {
            unsigned q0 = (unsigned)normq(f0[j], mnf, den);
            unsigned q1 = (unsigned)normq(f1[j], mnf, den);
            unsigned q2 = (unsigned)normq(f2[j], mnf, den);
            px[j] = q0 | (q1 << 8) | (q2 << 16);
            unsigned a = ((fixmask >> j) & 1u) ? ((cenmask >> j) & 1u)
                                               : ((mbits >> j) & 1u);
            if (j < 4) al |= a << (8*j); else ah |= a << (8*(j-4));
            s0 += q0*a; s1 += q1*a; s2 += q2*a; cnt += a;
            u0 += q0; u1 += q1; u2 += q2;
        }
        *(uint2*)&s_alpha[0][ry][x0] = make_uint2(al, ah);
        if ((ry == 0 && y > 0) || (ry == 3 && y < 511))
            __stcg((uint2*)(g_alpha[0] + p0), make_uint2(al, ah));

        unsigned v[7] = {s0, s1, s2, cnt, u0, u1, u2};
        #pragma unroll
        for (int j = 0; j < 7; j++) {
            unsigned w = __reduce_add_sync(0xFFFFFFFFu, v[j]);
            if (lane == 0) s_su[j*8 + warp] = w;
        }
        __syncthreads();
        if (warp == 0) {
            #pragma unroll
            for (int j = 0; j < 7; j++) {
                unsigned acc = (lane < 8) ? s_su[j*8 + lane] : 0u;
                acc = __reduce_add_sync(0xFFFFFFFFu, acc);
                if (lane == 0) {
                    if (j < 3)       atomicAdd(&g_fgsum[0][b][j], acc);
                    else if (j == 3) atomicAdd(&g_fgcnt[0][b], acc);
                    else             atomicAdd(&g_tot[b][j-4], acc);
                }
            }
        }
    }
    bar += GRID; gridbar(bar);

    // ======== phase 3: 5 ICM iterations ========
    #pragma unroll
    for (int k = 0; k < 5; k++) {
        const int cur = k & 1, nxt = cur ^ 1;
        const bool last = (k == 4);

        // means: threads 0..5, each computes one value (parallel L2 loads)
        if (t < 6) {
            float cntf = (float)__ldcg(&g_fgcnt[k][b]);
            if (t < 3) {
                unsigned fs = __ldcg(&g_fgsum[k][b][t]);
                s_means[t] = __fdiv_rn((float)fs, __fadd_rn(cntf, 1e-6f));
            } else {
                unsigned fs = __ldcg(&g_fgsum[k][b][t-3]);
                unsigned tt = __ldcg(&g_tot[b][t-3]);
                s_means[t] = __fdiv_rn((float)(tt - fs),
                                       __fadd_rn(__fsub_rn((float)HW, cntf), 1e-6f));
            }
        }
        // neighbor fetch overlapped with means loads (s_alpha[cur] synced last iter)
        uint2 up, dn;
        if (ry == 0) up = (y == 0)   ? make_uint2(al, ah)
                                     : __ldcg((const uint2*)(g_alpha[cur] + p0 - WW));
        else         up = *(const uint2*)&s_alpha[cur][ry-1][x0];
        if (ry == 3) dn = (y == 511) ? make_uint2(al, ah)
                                     : __ldcg((const uint2*)(g_alpha[cur] + p0 + WW));
        else         dn = *(const uint2*)&s_alpha[cur][ry+1][x0];
        int lft = (x0 == 0)   ? (int)(al & 255u)         : (int)s_alpha[cur][ry][x0-1];
        int rgt = (x0 == 504) ? (int)((ah >> 24) & 255u) : (int)s_alpha[cur][ry][x0+8];
        __syncthreads();
        const float fm0 = s_means[0], fm1 = s_means[1], fm2 = s_means[2];
        const float bm0 = s_means[3], bm1 = s_means[4], bm2 = s_means[5];

        int sb[10];
        sb[0] = lft;
        sb[1] =  al        & 255; sb[2] = (al >> 8)  & 255;
        sb[3] = (al >> 16) & 255; sb[4] = (al >> 24) & 255;
        sb[5] =  ah        & 255; sb[6] = (ah >> 8)  & 255;
        sb[7] = (ah >> 16) & 255; sb[8] = (ah >> 24) & 255;
        sb[9] = rgt;
        int ub[8] = { (int)(up.x & 255), (int)((up.x >> 8) & 255),
                      (int)((up.x >> 16) & 255), (int)((up.x >> 24) & 255),
                      (int)(up.y & 255), (int)((up.y >> 8) & 255),
                      (int)((up.y >> 16) & 255), (int)((up.y >> 24) & 255) };
        int db[8] = { (int)(dn.x & 255), (int)((dn.x >> 8) & 255),
                      (int)((dn.x >> 16) & 255), (int)((dn.x >> 24) & 255),
                      (int)(dn.y & 255), (int)((dn.y >> 8) & 255),
                      (int)((dn.y >> 16) & 255), (int)((dn.y >> 24) & 255) };

        unsigned nl = 0, nh = 0;
        unsigned s0 = 0, s1 = 0, s2 = 0, cnt = 0;
        float o[8];
        #pragma unroll
        for (int j = 0; j < 8; j++) {
            unsigned q0 =  px[j]        & 255u;
            unsigned q1 = (px[j] >> 8)  & 255u;
            unsigned q2 = (px[j] >> 16) & 255u;
            float i0 = (float)q0, i1 = (float)q1, i2 = (float)q2;
            int n = ub[j] + db[j] + sb[j] + sb[j + 2];
            float pw = (float)(25 * n - 50);       // == 50*(2*(n/4)-1) exactly

            float d0 = __fsub_rn(i0, fm0), d1 = __fsub_rn(i1, fm1), d2 = __fsub_rn(i2, fm2);
            float dfg = __fadd_rn(__fadd_rn(__fmul_rn(d0, d0), __fmul_rn(d1, d1)),
                                  __fmul_rn(d2, d2));
            float e0 = __fsub_rn(i0, bm0), e1 = __fsub_rn(i1, bm1), e2 = __fsub_rn(i2, bm2);
            float dbg = __fadd_rn(__fadd_rn(__fmul_rn(e0, e0), __fmul_rn(e1, e1)),
                                  __fmul_rn(e2, e2));
            float score = __fadd_rn(__fsub_rn(dbg, dfg), pw);

            unsigned a = ((fixmask >> j) & 1u) ? ((cenmask >> j) & 1u)
                                               : (score > 0.0f ? 1u : 0u);
            if (j < 4) nl |= a << (8*j); else nh |= a << (8*(j-4));
            if (!last) { s0 += q0*a; s1 += q1*a; s2 += q2*a; cnt += a; }
            else o[j] = (float)a;
        }
        al = nl; ah = nh;

        if (!last) {
            *(uint2*)&s_alpha[nxt][ry][x0] = make_uint2(nl, nh);
            if ((ry == 0 && y > 0) || (ry == 3 && y < 511))
                __stcg((uint2*)(g_alpha[nxt] + p0), make_uint2(nl, nh));

            unsigned v[4] = {s0, s1, s2, cnt};
            #pragma unroll
            for (int j = 0; j < 4; j++) {
                unsigned w = __reduce_add_sync(0xFFFFFFFFu, v[j]);
                if (lane == 0) s_su[j*8 + warp] = w;
            }
            __syncthreads();
            if (warp == 0) {
                #pragma unroll
                for (int j = 0; j < 4; j++) {
                    unsigned acc = (lane < 8) ? s_su[j*8 + lane] : 0u;
                    acc = __reduce_add_sync(0xFFFFFFFFu, acc);
                    if (lane == 0) {
                        if (j < 3) atomicAdd(&g_fgsum[k+1][b][j], acc);
                        else       atomicAdd(&g_fgcnt[k+1][b], acc);
                    }
                }
            }
            bar += GRID; gridbar(bar);
        } else {
            *(float4*)(out + p0)     = make_float4(o[0], o[1], o[2], o[3]);
            *(float4*)(out + p0 + 4) = make_float4(o[4], o[5], o[6], o[7]);
        }
    }
}

extern "C" void kernel_launch(void* const* d_in, const int* in_sizes, int n_in,
                              void* d_out, int out_size) {
    const float* feat = (const float*)d_in[0];
    const int*   mask = (const int*)d_in[1];
    float*       out  = (float*)d_out;

    k_init<<<1, 64>>>();
    k_fused<<<GRID, TPB>>>(feat, mask, out);
}